// round 8
// baseline (speedup 1.0000x reference)
#include <cuda_runtime.h>
#include <cuda_bf16.h>

// ---------------------------------------------------------------------------
// VoxelDistill: heatmap (centerpoint-style gaussian max, SCATTER form) +
// fused conv1x1 -> trilinear-downsample -> masked L1 distill loss.
//
// Algebra: all three lin_resize stages have weight exactly 0.5, so
// resize(conv(x)) == conv(avg8(x)). Average the 8 student taps per channel
// (d in {4D+1,4D+2}, h in {2H,2H+1}, w in {2W,2W+1}), then one 128x64
// matvec per output position, done as packed f32x2 FFMA2.
//
// 3 graph nodes: memset(g_hm+sum) -> scatter heatmap (atomicMax + exact
// telescoping delta-sum) -> fused main.
// ---------------------------------------------------------------------------

#define EPS32F 1.1920928955078125e-7f
#define HM_CELLS (2 * 128 * 128)

__device__ float g_hm[HM_CELLS + 1];   // [D][H][W]; [HM_CELLS] = heatmap sum

__device__ __forceinline__ float gauss_radius(float h, float w) {
    const float ov = 0.1f;
    float b1 = h + w;
    float c1 = w * h * (1.0f - ov) / (1.0f + ov);
    float r1 = (b1 + sqrtf(fmaxf(b1 * b1 - 4.0f * c1, 0.0f))) / 2.0f;
    float b2 = 2.0f * (h + w);
    float c2 = (1.0f - ov) * w * h;
    float r2 = (b2 + sqrtf(fmaxf(b2 * b2 - 16.0f * c2, 0.0f))) / 2.0f;
    float b3 = -2.0f * ov * (h + w);
    float c3 = (ov - 1.0f) * w * h;
    float r3 = (b3 + sqrtf(fmaxf(b3 * b3 - 16.0f * ov * c3, 0.0f))) / 2.0f;
    return fminf(fminf(r1, r2), r3);
}

__device__ __forceinline__ void fma2(unsigned long long& d,
                                     unsigned long long a,
                                     unsigned long long b) {
    asm("fma.rn.f32x2 %0, %1, %2, %0;" : "+l"(d) : "l"(a), "l"(b));
}

// One block per box; threads cover the (clipped) gaussian window.
__global__ void __launch_bounds__(256)
vd_scatter_kernel(const float* __restrict__ boxes) {
    const float* B = boxes + blockIdx.x * 9;
    float bx = B[0], by = B[1], bz = B[2];
    float wf = B[3] / 0.1f / 8.0f;
    float lf = B[4] / 0.1f / 8.0f;
    float hf = B[5] / 0.2f / 8.0f;

    float r_xy = gauss_radius(lf, wf);
    float r_z  = fmaxf(gauss_radius(lf, hf), gauss_radius(wf, hf));
    int rx = max(2, (int)(r_xy / 0.4f));   // trunc toward zero, matches jnp
    int rz = max(2, (int)(r_z  / 1.0f));

    int cxi = (int)((bx + 51.2f) / 0.4f);
    int cyi = (int)((by + 51.2f) / 0.4f);
    int czi = (int)((bz + 5.0f)  / 1.0f);

    bool valid = (wf > 0.0f) && (lf > 0.0f) &&
                 (cxi >= 0) && (cxi < 128) &&
                 (cyi >= 0) && (cyi < 128) &&
                 (czi >= 0) && (czi <= 1);
    if (!valid) return;

    float sx = (2.0f * (float)rx + 1.0f) / 6.0f;
    float sz = (2.0f * (float)rz + 1.0f) / 6.0f;
    float dnx = 2.0f * sx * sx;            // sy == sx since ry == rx
    float dnz = 2.0f * sz * sz;

    int x0 = max(0, cxi - rx), x1 = min(127, cxi + rx);
    int y0 = max(0, cyi - rx), y1 = min(127, cyi + rx);
    int z0 = max(0, czi - rz), z1 = min(1,   czi + rz);
    int nx = x1 - x0 + 1, ny = y1 - y0 + 1, nz = z1 - z0 + 1;
    int nxy = nx * ny;
    int total = nxy * nz;

    for (int idx = threadIdx.x; idx < total; idx += 256) {
        int iz = idx / nxy;
        int r  = idx - iz * nxy;
        int iy = r / nx;
        int ix = r - iy * nx;
        int X = x0 + ix, Y = y0 + iy, Z = z0 + iz;
        int dx = X - cxi, dy = Y - cyi, dz = Z - czi;
        float e = (float)(dx * dx) / dnx
                + (float)(dy * dy) / dnx
                + (float)(dz * dz) / dnz;
        float g = expf(-e);
        if (g >= EPS32F) {
            int cell = Z * 16384 + X * 128 + Y;   // [D][H=x][W=y]
            int gi = __float_as_int(g);
            int old = atomicMax((int*)&g_hm[cell], gi);
            if (old < gi)   // deltas telescope to the final per-cell max
                atomicAdd(&g_hm[HM_CELLS], g - __int_as_float(old));
        }
    }
}

// grid (2, 128, 2): block covers 64 output W at fixed (H, D). 256 threads.
// Lane l handles positions wi = 2l (row l) and 2l+1 (row 32+l); warp og
// handles 16 output channels. FFMA2 packs channel pairs.
#define AVG_STRIDE 68   // ≡ 4 (mod 32) -> conflict-free LDS.128

__global__ void __launch_bounds__(256, 8)
vd_main_kernel(const float* __restrict__ student,
               const float* __restrict__ teacher,
               const float* __restrict__ conv_w,
               const float* __restrict__ conv_b,
               float* __restrict__ out) {
    __shared__ float sh_avg[64 * AVG_STRIDE];   // ~17.4 KB

    int t  = threadIdx.x;
    int W0 = blockIdx.x * 64;
    int H  = blockIdx.y;
    int D  = blockIdx.z;

    // Phase 1: 8-tap average of student into shared (float4 loads).
    // student layout: c:524288, d:65536, h:256, w:1
    // task e: c = e>>5, pair p = e&31 -> wi = 2p (row p), 2p+1 (row 32+p)
    {
        int d0 = 4 * D + 1;
        int h0 = 2 * H;
        const float4* sp4 = (const float4*)student;
        #pragma unroll
        for (int i = 0; i < 8; i++) {
            int e = t + i * 256;
            int c = e >> 5;
            int p = e & 31;
            int fbase = c * 524288 + d0 * 65536 + h0 * 256 + 2 * W0 + 4 * p;
            int b4 = fbase >> 2;
            float4 q0 = sp4[b4];                    // d0,   h0
            float4 q1 = sp4[b4 + 64];               // d0,   h0+1
            float4 q2 = sp4[b4 + 16384];            // d0+1, h0
            float4 q3 = sp4[b4 + 16384 + 64];       // d0+1, h0+1
            sh_avg[p * AVG_STRIDE + c] =
                (q0.x + q0.y + q1.x + q1.y + q2.x + q2.y + q3.x + q3.y) * 0.125f;
            sh_avg[(32 + p) * AVG_STRIDE + c] =
                (q0.z + q0.w + q1.z + q1.w + q2.z + q2.w + q3.z + q3.w) * 0.125f;
        }
    }
    __syncthreads();

    int l  = t & 31;
    int og = t >> 5;

    unsigned long long accA[16], accB[16];
    #pragma unroll
    for (int k = 0; k < 16; k++) { accA[k] = 0ull; accB[k] = 0ull; }

    const ulonglong2* w2p = (const ulonglong2*)conv_w;   // [o][c] rows, 16B granules

    #pragma unroll 1
    for (int c4i = 0; c4i < 16; c4i++) {
        int c4 = c4i * 4;
        // values: LDS.128 -> two natural f32x2 register pairs each
        ulonglong2 va = *(const ulonglong2*)&sh_avg[l * AVG_STRIDE + c4];
        ulonglong2 vb = *(const ulonglong2*)&sh_avg[(32 + l) * AVG_STRIDE + c4];
        #pragma unroll
        for (int k = 0; k < 16; k++) {
            // weights: LDG.128, warp-uniform broadcast, L1/L2 resident
            ulonglong2 w = __ldg(&w2p[((og * 16 + k) * 64 + c4) >> 2]);
            fma2(accA[k], w.x, va.x);
            fma2(accA[k], w.y, va.y);
            fma2(accB[k], w.x, vb.x);
            fma2(accB[k], w.y, vb.y);
        }
    }

    // Epilogue: loss = |conv + b - teacher| * hm * 10 / (sum + 1e-4)
    float scale = 10.0f / (g_hm[HM_CELLS] + 1e-4f);
    int sp0 = D * 16384 + H * 128 + W0 + 2 * l;     // spatial index (D,H,W)
    float2 hm2 = *(const float2*)&g_hm[sp0];
    float f0 = hm2.x * scale;
    float f1 = hm2.y * scale;

    #pragma unroll
    for (int k = 0; k < 16; k++) {
        int o   = og * 16 + k;
        int idx = o * 32768 + sp0;
        float a0, a1, b0, b1;
        asm("mov.b64 {%0,%1}, %2;" : "=f"(a0), "=f"(a1) : "l"(accA[k]));
        asm("mov.b64 {%0,%1}, %2;" : "=f"(b0), "=f"(b1) : "l"(accB[k]));
        float bk = __ldg(&conv_b[o]);
        float2 t2 = *(const float2*)&teacher[idx];
        float2 r;
        r.x = fabsf((a0 + a1) + bk - t2.x) * f0;
        r.y = fabsf((b0 + b1) + bk - t2.y) * f1;
        *(float2*)&out[idx] = r;
    }
}

extern "C" void kernel_launch(void* const* d_in, const int* in_sizes, int n_in,
                              void* d_out, int out_size) {
    const float* boxes   = (const float*)d_in[0];
    // d_in[1] = gt_labels_3d (unused by reference)
    const float* teacher = (const float*)d_in[2];
    const float* student = (const float*)d_in[3];
    const float* conv_w  = (const float*)d_in[4];
    const float* conv_b  = (const float*)d_in[5];
    int N = in_sizes[0] / 9;

    void* hm_ptr = nullptr;
    cudaGetSymbolAddress(&hm_ptr, g_hm);
    cudaMemsetAsync(hm_ptr, 0, (HM_CELLS + 1) * sizeof(float), 0);

    if (N > 0) vd_scatter_kernel<<<N, 256>>>(boxes);

    dim3 grid(2, 128, 2);
    vd_main_kernel<<<grid, 256>>>(student, teacher, conv_w, conv_b,
                                  (float*)d_out);
}

// round 9
// speedup vs baseline: 7.6268x; 7.6268x over previous
#include <cuda_runtime.h>
#include <cuda_bf16.h>

// ---------------------------------------------------------------------------
// VoxelDistill: heatmap (centerpoint-style gaussian max, SCATTER form) +
// fused conv1x1 -> trilinear-downsample -> masked L1 distill loss.
//
// Algebra: all three lin_resize stages have weight exactly 0.5, so
// resize(conv(x)) == conv(avg8(x)). Average the 8 student taps per channel
// (d in {4D+1,4D+2}, h in {2H,2H+1}, w in {2W,2W+1}), then one 128x64
// matvec per output position, as packed f32x2 FFMA2 over channel pairs.
//
// 3 graph nodes: memset(g_hm+sum) -> scatter heatmap (atomicMax + exact
// telescoping delta-sum, ONE atomicAdd per block) -> fused main.
// ---------------------------------------------------------------------------

#define EPS32F 1.1920928955078125e-7f
#define HM_CELLS (2 * 128 * 128)

__device__ float g_hm[HM_CELLS + 1];   // [D][H][W]; [HM_CELLS] = heatmap sum

__device__ __forceinline__ float gauss_radius(float h, float w) {
    const float ov = 0.1f;
    float b1 = h + w;
    float c1 = w * h * (1.0f - ov) / (1.0f + ov);
    float r1 = (b1 + sqrtf(fmaxf(b1 * b1 - 4.0f * c1, 0.0f))) / 2.0f;
    float b2 = 2.0f * (h + w);
    float c2 = (1.0f - ov) * w * h;
    float r2 = (b2 + sqrtf(fmaxf(b2 * b2 - 16.0f * c2, 0.0f))) / 2.0f;
    float b3 = -2.0f * ov * (h + w);
    float c3 = (ov - 1.0f) * w * h;
    float r3 = (b3 + sqrtf(fmaxf(b3 * b3 - 16.0f * ov * c3, 0.0f))) / 2.0f;
    return fminf(fminf(r1, r2), r3);
}

__device__ __forceinline__ void fma2(unsigned long long& d,
                                     unsigned long long a,
                                     unsigned long long b) {
    asm("fma.rn.f32x2 %0, %1, %2, %0;" : "+l"(d) : "l"(a), "l"(b));
}

// One block per box; threads cover the (clipped) gaussian window.
// Sum deltas accumulate per-thread, block-reduce, ONE atomicAdd per block.
__global__ void __launch_bounds__(256)
vd_scatter_kernel(const float* __restrict__ boxes) {
    __shared__ float s_red[8];
    const float* B = boxes + blockIdx.x * 9;
    float bx = B[0], by = B[1], bz = B[2];
    float wf = B[3] / 0.1f / 8.0f;
    float lf = B[4] / 0.1f / 8.0f;
    float hf = B[5] / 0.2f / 8.0f;

    float r_xy = gauss_radius(lf, wf);
    float r_z  = fmaxf(gauss_radius(lf, hf), gauss_radius(wf, hf));
    int rx = max(2, (int)(r_xy / 0.4f));   // trunc toward zero, matches jnp
    int rz = max(2, (int)(r_z  / 1.0f));

    int cxi = (int)((bx + 51.2f) / 0.4f);
    int cyi = (int)((by + 51.2f) / 0.4f);
    int czi = (int)((bz + 5.0f)  / 1.0f);

    bool valid = (wf > 0.0f) && (lf > 0.0f) &&
                 (cxi >= 0) && (cxi < 128) &&
                 (cyi >= 0) && (cyi < 128) &&
                 (czi >= 0) && (czi <= 1);
    if (!valid) return;

    float sx = (2.0f * (float)rx + 1.0f) / 6.0f;
    float sz = (2.0f * (float)rz + 1.0f) / 6.0f;
    float dnx = 2.0f * sx * sx;            // sy == sx since ry == rx
    float dnz = 2.0f * sz * sz;

    int x0 = max(0, cxi - rx), x1 = min(127, cxi + rx);
    int y0 = max(0, cyi - rx), y1 = min(127, cyi + rx);
    int z0 = max(0, czi - rz), z1 = min(1,   czi + rz);
    int nx = x1 - x0 + 1, ny = y1 - y0 + 1, nz = z1 - z0 + 1;
    int nxy = nx * ny;
    int total = nxy * nz;

    float delta = 0.0f;
    for (int idx = threadIdx.x; idx < total; idx += 256) {
        int iz = idx / nxy;
        int r  = idx - iz * nxy;
        int iy = r / nx;
        int ix = r - iy * nx;
        int X = x0 + ix, Y = y0 + iy, Z = z0 + iz;
        int dx = X - cxi, dy = Y - cyi, dz = Z - czi;
        float e = (float)(dx * dx) / dnx
                + (float)(dy * dy) / dnx
                + (float)(dz * dz) / dnz;
        float g = expf(-e);
        if (g >= EPS32F) {
            int cell = Z * 16384 + X * 128 + Y;   // [D][H=x][W=y]
            int gi = __float_as_int(g);
            int old = atomicMax((int*)&g_hm[cell], gi);
            if (old < gi)   // deltas telescope to the per-cell max; additive
                delta += g - __int_as_float(old);
        }
    }

    int t = threadIdx.x;
    #pragma unroll
    for (int o = 16; o; o >>= 1) delta += __shfl_down_sync(0xffffffffu, delta, o);
    if ((t & 31) == 0) s_red[t >> 5] = delta;
    __syncthreads();
    if (t < 32) {
        float s = (t < 8) ? s_red[t] : 0.0f;
        #pragma unroll
        for (int o = 4; o; o >>= 1) s += __shfl_down_sync(0xffffffffu, s, o);
        if (t == 0) atomicAdd(&g_hm[HM_CELLS], s);
    }
}

// grid (2, 128, 2): block covers 64 output W at fixed (H, D). 256 threads.
// Lane l handles wi = 2l (row l of sh_avg) and 2l+1 (row 32+l); warp og
// handles 16 output channels in 2 passes of 8 (caps live accumulators).
#define AVG_STRIDE 68   // words; ≡4 mod 32 -> conflict-free LDS.128 per quarter-warp

__global__ void __launch_bounds__(256)
vd_main_kernel(const float* __restrict__ student,
               const float* __restrict__ teacher,
               const float* __restrict__ conv_w,
               const float* __restrict__ conv_b,
               float* __restrict__ out) {
    __shared__ __align__(16) float sh_w[128 * 64];        // 32 KB
    __shared__ __align__(16) float sh_avg[64 * AVG_STRIDE];

    int t  = threadIdx.x;
    int W0 = blockIdx.x * 64;
    int H  = blockIdx.y;
    int D  = blockIdx.z;

    // stage conv_w (float4)
    {
        const float4* w4p = (const float4*)conv_w;
        float4*       s4p = (float4*)sh_w;
        #pragma unroll
        for (int i = t; i < 2048; i += 256) s4p[i] = w4p[i];
    }

    // Phase 1: 8-tap average of student into shared (float4 loads).
    // student layout: c:524288, d:65536, h:256, w:1
    // task e: c = e>>5, pair p = e&31 -> wi = 2p (row p), 2p+1 (row 32+p)
    {
        int d0 = 4 * D + 1;
        int h0 = 2 * H;
        const float4* sp4 = (const float4*)student;
        #pragma unroll
        for (int i = 0; i < 8; i++) {
            int e = t + i * 256;
            int c = e >> 5;
            int p = e & 31;
            int fbase = c * 524288 + d0 * 65536 + h0 * 256 + 2 * W0 + 4 * p;
            int b4 = fbase >> 2;
            float4 q0 = sp4[b4];                    // d0,   h0
            float4 q1 = sp4[b4 + 64];               // d0,   h0+1
            float4 q2 = sp4[b4 + 16384];            // d0+1, h0
            float4 q3 = sp4[b4 + 16384 + 64];       // d0+1, h0+1
            sh_avg[p * AVG_STRIDE + c] =
                (q0.x + q0.y + q1.x + q1.y + q2.x + q2.y + q3.x + q3.y) * 0.125f;
            sh_avg[(32 + p) * AVG_STRIDE + c] =
                (q0.z + q0.w + q1.z + q1.w + q2.z + q2.w + q3.z + q3.w) * 0.125f;
        }
    }
    __syncthreads();

    int l  = t & 31;
    int og = t >> 5;

    // Epilogue constants
    float scale = 10.0f / (g_hm[HM_CELLS] + 1e-4f);
    int sp0 = D * 16384 + H * 128 + W0 + 2 * l;     // spatial index (D,H,W)
    float2 hm2 = *(const float2*)&g_hm[sp0];
    float f0 = hm2.x * scale;
    float f1 = hm2.y * scale;

    #pragma unroll
    for (int pass = 0; pass < 2; pass++) {
        unsigned long long accA[8], accB[8];
        #pragma unroll
        for (int k = 0; k < 8; k++) { accA[k] = 0ull; accB[k] = 0ull; }

        int obase = og * 16 + pass * 8;

        #pragma unroll
        for (int c4i = 0; c4i < 16; c4i++) {
            int c4 = c4i * 4;
            // values: LDS.128 -> two natural f32x2 register pairs each
            ulonglong2 va = *(const ulonglong2*)&sh_avg[l * AVG_STRIDE + c4];
            ulonglong2 vb = *(const ulonglong2*)&sh_avg[(32 + l) * AVG_STRIDE + c4];
            #pragma unroll
            for (int k = 0; k < 8; k++) {
                // weights: LDS.128 warp-uniform broadcast
                ulonglong2 w = *(const ulonglong2*)&sh_w[(obase + k) * 64 + c4];
                fma2(accA[k], w.x, va.x);
                fma2(accA[k], w.y, va.y);
                fma2(accB[k], w.x, vb.x);
                fma2(accB[k], w.y, vb.y);
            }
        }

        // Epilogue: loss = |conv + b - teacher| * hm * 10 / (sum + 1e-4)
        #pragma unroll
        for (int k = 0; k < 8; k++) {
            int o   = obase + k;
            int idx = o * 32768 + sp0;
            float a0, a1, b0, b1;
            asm("mov.b64 {%0,%1}, %2;" : "=f"(a0), "=f"(a1) : "l"(accA[k]));
            asm("mov.b64 {%0,%1}, %2;" : "=f"(b0), "=f"(b1) : "l"(accB[k]));
            float bk = __ldg(&conv_b[o]);
            float2 t2 = *(const float2*)&teacher[idx];
            float2 r;
            r.x = fabsf((a0 + a1) + bk - t2.x) * f0;
            r.y = fabsf((b0 + b1) + bk - t2.y) * f1;
            *(float2*)&out[idx] = r;
        }
    }
}

extern "C" void kernel_launch(void* const* d_in, const int* in_sizes, int n_in,
                              void* d_out, int out_size) {
    const float* boxes   = (const float*)d_in[0];
    // d_in[1] = gt_labels_3d (unused by reference)
    const float* teacher = (const float*)d_in[2];
    const float* student = (const float*)d_in[3];
    const float* conv_w  = (const float*)d_in[4];
    const float* conv_b  = (const float*)d_in[5];
    int N = in_sizes[0] / 9;

    void* hm_ptr = nullptr;
    cudaGetSymbolAddress(&hm_ptr, g_hm);
    cudaMemsetAsync(hm_ptr, 0, (HM_CELLS + 1) * sizeof(float), 0);

    if (N > 0) vd_scatter_kernel<<<N, 256>>>(boxes);

    dim3 grid(2, 128, 2);
    vd_main_kernel<<<grid, 256>>>(student, teacher, conv_w, conv_b,
                                  (float*)d_out);
}

// round 10
// speedup vs baseline: 7.9589x; 1.0435x over previous
#include <cuda_runtime.h>
#include <cuda_bf16.h>

// ---------------------------------------------------------------------------
// VoxelDistill: heatmap (centerpoint-style gaussian max, SCATTER form) +
// fused conv1x1 -> trilinear-downsample -> masked L1 distill loss.
//
// Algebra: all three lin_resize stages have weight exactly 0.5, so
// resize(conv(x)) == conv(avg8(x)). Average the 8 student taps per channel
// (d in {4D+1,4D+2}, h in {2H,2H+1}, w in {2W,2W+1}), then one 128x64
// matvec per output position, as packed f32x2 FFMA2 over channel pairs.
//
// 3 graph nodes: memset(g_hm+sum) -> scatter heatmap (atomicMax + exact
// telescoping delta-sum, ONE atomicAdd per block) -> fused main.
// ---------------------------------------------------------------------------

#define EPS32F 1.1920928955078125e-7f
#define HM_CELLS (2 * 128 * 128)

__device__ float g_hm[HM_CELLS + 1];   // [D][H][W]; [HM_CELLS] = heatmap sum

__device__ __forceinline__ float gauss_radius(float h, float w) {
    const float ov = 0.1f;
    float b1 = h + w;
    float c1 = w * h * (1.0f - ov) / (1.0f + ov);
    float r1 = (b1 + sqrtf(fmaxf(b1 * b1 - 4.0f * c1, 0.0f))) / 2.0f;
    float b2 = 2.0f * (h + w);
    float c2 = (1.0f - ov) * w * h;
    float r2 = (b2 + sqrtf(fmaxf(b2 * b2 - 16.0f * c2, 0.0f))) / 2.0f;
    float b3 = -2.0f * ov * (h + w);
    float c3 = (ov - 1.0f) * w * h;
    float r3 = (b3 + sqrtf(fmaxf(b3 * b3 - 16.0f * ov * c3, 0.0f))) / 2.0f;
    return fminf(fminf(r1, r2), r3);
}

__device__ __forceinline__ void fma2(unsigned long long& d,
                                     unsigned long long a,
                                     unsigned long long b) {
    asm("fma.rn.f32x2 %0, %1, %2, %0;" : "+l"(d) : "l"(a), "l"(b));
}

// One block per box; threads cover the (clipped) gaussian window.
// Sum deltas accumulate per-thread, block-reduce, ONE atomicAdd per block.
__global__ void __launch_bounds__(256)
vd_scatter_kernel(const float* __restrict__ boxes) {
    __shared__ float s_red[8];
    const float* B = boxes + blockIdx.x * 9;
    float bx = B[0], by = B[1], bz = B[2];
    float wf = B[3] / 0.1f / 8.0f;
    float lf = B[4] / 0.1f / 8.0f;
    float hf = B[5] / 0.2f / 8.0f;

    float r_xy = gauss_radius(lf, wf);
    float r_z  = fmaxf(gauss_radius(lf, hf), gauss_radius(wf, hf));
    int rx = max(2, (int)(r_xy / 0.4f));   // trunc toward zero, matches jnp
    int rz = max(2, (int)(r_z  / 1.0f));

    int cxi = (int)((bx + 51.2f) / 0.4f);
    int cyi = (int)((by + 51.2f) / 0.4f);
    int czi = (int)((bz + 5.0f)  / 1.0f);

    bool valid = (wf > 0.0f) && (lf > 0.0f) &&
                 (cxi >= 0) && (cxi < 128) &&
                 (cyi >= 0) && (cyi < 128) &&
                 (czi >= 0) && (czi <= 1);
    if (!valid) return;

    float sx = (2.0f * (float)rx + 1.0f) / 6.0f;
    float sz = (2.0f * (float)rz + 1.0f) / 6.0f;
    float dnx = 2.0f * sx * sx;            // sy == sx since ry == rx
    float dnz = 2.0f * sz * sz;

    int x0 = max(0, cxi - rx), x1 = min(127, cxi + rx);
    int y0 = max(0, cyi - rx), y1 = min(127, cyi + rx);
    int z0 = max(0, czi - rz), z1 = min(1,   czi + rz);
    int nx = x1 - x0 + 1, ny = y1 - y0 + 1, nz = z1 - z0 + 1;
    int nxy = nx * ny;
    int total = nxy * nz;

    float delta = 0.0f;
    for (int idx = threadIdx.x; idx < total; idx += 256) {
        int iz = idx / nxy;
        int r  = idx - iz * nxy;
        int iy = r / nx;
        int ix = r - iy * nx;
        int X = x0 + ix, Y = y0 + iy, Z = z0 + iz;
        int dx = X - cxi, dy = Y - cyi, dz = Z - czi;
        float e = (float)(dx * dx) / dnx
                + (float)(dy * dy) / dnx
                + (float)(dz * dz) / dnz;
        float g = expf(-e);
        if (g >= EPS32F) {
            int cell = Z * 16384 + X * 128 + Y;   // [D][H=x][W=y]
            int gi = __float_as_int(g);
            int old = atomicMax((int*)&g_hm[cell], gi);
            if (old < gi)   // deltas telescope to the per-cell max; additive
                delta += g - __int_as_float(old);
        }
    }

    int t = threadIdx.x;
    #pragma unroll
    for (int o = 16; o; o >>= 1) delta += __shfl_down_sync(0xffffffffu, delta, o);
    if ((t & 31) == 0) s_red[t >> 5] = delta;
    __syncthreads();
    if (t < 32) {
        float s = (t < 8) ? s_red[t] : 0.0f;
        #pragma unroll
        for (int o = 4; o; o >>= 1) s += __shfl_down_sync(0xffffffffu, s, o);
        if (t == 0) atomicAdd(&g_hm[HM_CELLS], s);
    }
}

// grid (2, 128, 2): block covers 64 output W at fixed (H, D). 256 threads.
// Lane l handles wi = 2l (row l of sh_avg) and 2l+1 (row 32+l); warp og
// handles 16 output channels in 2 passes of 8 (caps live accumulators at
// 16 x u64 = 32 regs). __launch_bounds__(256,3) caps regs ~84 (R7's proven
// sweet spot: no spill, 4 CTAs/SM).
#define AVG_STRIDE 68   // words; ≡4 mod 32 -> conflict-free LDS.128

__global__ void __launch_bounds__(256, 3)
vd_main_kernel(const float* __restrict__ student,
               const float* __restrict__ teacher,
               const float* __restrict__ conv_w,
               const float* __restrict__ conv_b,
               float* __restrict__ out) {
    __shared__ __align__(16) float sh_w[128 * 64];        // 32 KB
    __shared__ __align__(16) float sh_avg[64 * AVG_STRIDE];

    int t  = threadIdx.x;
    int W0 = blockIdx.x * 64;
    int H  = blockIdx.y;
    int D  = blockIdx.z;

    // stage conv_w (float4)
    {
        const float4* w4p = (const float4*)conv_w;
        float4*       s4p = (float4*)sh_w;
        #pragma unroll
        for (int i = t; i < 2048; i += 256) s4p[i] = w4p[i];
    }

    // Phase 1: 8-tap average of student into shared (float4 loads).
    // student layout: c:524288, d:65536, h:256, w:1
    // task e: c = e>>5, pair p = e&31 -> wi = 2p (row p), 2p+1 (row 32+p)
    {
        int d0 = 4 * D + 1;
        int h0 = 2 * H;
        const float4* sp4 = (const float4*)student;
        #pragma unroll
        for (int i = 0; i < 8; i++) {
            int e = t + i * 256;
            int c = e >> 5;
            int p = e & 31;
            int fbase = c * 524288 + d0 * 65536 + h0 * 256 + 2 * W0 + 4 * p;
            int b4 = fbase >> 2;
            float4 q0 = sp4[b4];                    // d0,   h0
            float4 q1 = sp4[b4 + 64];               // d0,   h0+1
            float4 q2 = sp4[b4 + 16384];            // d0+1, h0
            float4 q3 = sp4[b4 + 16384 + 64];       // d0+1, h0+1
            sh_avg[p * AVG_STRIDE + c] =
                (q0.x + q0.y + q1.x + q1.y + q2.x + q2.y + q3.x + q3.y) * 0.125f;
            sh_avg[(32 + p) * AVG_STRIDE + c] =
                (q0.z + q0.w + q1.z + q1.w + q2.z + q2.w + q3.z + q3.w) * 0.125f;
        }
    }
    __syncthreads();

    int l  = t & 31;
    int og = t >> 5;

    // Epilogue constants
    float scale = 10.0f / (g_hm[HM_CELLS] + 1e-4f);
    int sp0 = D * 16384 + H * 128 + W0 + 2 * l;     // spatial index (D,H,W)
    float2 hm2 = *(const float2*)&g_hm[sp0];
    float f0 = hm2.x * scale;
    float f1 = hm2.y * scale;

    #pragma unroll
    for (int pass = 0; pass < 2; pass++) {
        unsigned long long accA[8], accB[8];
        #pragma unroll
        for (int k = 0; k < 8; k++) { accA[k] = 0ull; accB[k] = 0ull; }

        int obase = og * 16 + pass * 8;

        #pragma unroll 4
        for (int c4i = 0; c4i < 16; c4i++) {
            int c4 = c4i * 4;
            // values: LDS.128 -> two natural f32x2 register pairs each
            ulonglong2 va = *(const ulonglong2*)&sh_avg[l * AVG_STRIDE + c4];
            ulonglong2 vb = *(const ulonglong2*)&sh_avg[(32 + l) * AVG_STRIDE + c4];
            #pragma unroll
            for (int k = 0; k < 8; k++) {
                // weights: LDS.128 warp-uniform broadcast
                ulonglong2 w = *(const ulonglong2*)&sh_w[(obase + k) * 64 + c4];
                fma2(accA[k], w.x, va.x);
                fma2(accA[k], w.y, va.y);
                fma2(accB[k], w.x, vb.x);
                fma2(accB[k], w.y, vb.y);
            }
        }

        // Epilogue: loss = |conv + b - teacher| * hm * 10 / (sum + 1e-4)
        #pragma unroll
        for (int k = 0; k < 8; k++) {
            int o   = obase + k;
            int idx = o * 32768 + sp0;
            float a0, a1, b0, b1;
            asm("mov.b64 {%0,%1}, %2;" : "=f"(a0), "=f"(a1) : "l"(accA[k]));
            asm("mov.b64 {%0,%1}, %2;" : "=f"(b0), "=f"(b1) : "l"(accB[k]));
            float bk = __ldg(&conv_b[o]);
            float2 t2 = *(const float2*)&teacher[idx];
            float2 r;
            r.x = fabsf((a0 + a1) + bk - t2.x) * f0;
            r.y = fabsf((b0 + b1) + bk - t2.y) * f1;
            *(float2*)&out[idx] = r;
        }
    }
}

extern "C" void kernel_launch(void* const* d_in, const int* in_sizes, int n_in,
                              void* d_out, int out_size) {
    const float* boxes   = (const float*)d_in[0];
    // d_in[1] = gt_labels_3d (unused by reference)
    const float* teacher = (const float*)d_in[2];
    const float* student = (const float*)d_in[3];
    const float* conv_w  = (const float*)d_in[4];
    const float* conv_b  = (const float*)d_in[5];
    int N = in_sizes[0] / 9;

    void* hm_ptr = nullptr;
    cudaGetSymbolAddress(&hm_ptr, g_hm);
    cudaMemsetAsync(hm_ptr, 0, (HM_CELLS + 1) * sizeof(float), 0);

    if (N > 0) vd_scatter_kernel<<<N, 256>>>(boxes);

    dim3 grid(2, 128, 2);
    vd_main_kernel<<<grid, 256>>>(student, teacher, conv_w, conv_b,
                                  (float*)d_out);
}